// round 2
// baseline (speedup 1.0000x reference)
#include <cuda_runtime.h>

#define RCH 64
#define GCH 128
#define ACH 80
#define SCH 64
#define TT 8192
#define BB 8
#define NPOS (BB*TT)      // 65536
#define NLAYERS 30
#define POSB 128          // positions per block
#define THR 1024          // 8 threads per position
#define KCONV 192         // 3 taps * 64 ci
#define KTOT 272          // + 80 aux

// smem layout (bytes):
//   [0, 139264)        wsh64: 272 k * 64 pairs (u64)
//   [139264, 221184)   xbuf : staging buffer (x/cond tiles as dup-f32x2, weight scratch)
// reuse after gate:
//   [0, 65536)         zsh64: 64 ch * 128 pos (u64 dup)
//   [65536, 98304)     osh64: 64 k * 64 pairs (u64)
//   [98304, 131584)    scrO : 128*65 floats
#define WSH_BYTES (KTOT*64*8)
#define XBUF_BYTES (ACH*POSB*8)
#define SMEM_LAYER (WSH_BYTES + XBUF_BYTES)   // 221184

__device__ float g_xa[BB*RCH*TT];
__device__ float g_xb[BB*RCH*TT];
__device__ float g_skip[BB*SCH*TT];

typedef unsigned long long ull;

static __device__ __forceinline__ ull pk2(float lo, float hi) {
    ull r;
    asm("mov.b64 %0, {%1, %2};" : "=l"(r) : "f"(lo), "f"(hi));
    return r;
}
static __device__ __forceinline__ void upk2(ull v, float& lo, float& hi) {
    asm("mov.b64 {%0, %1}, %2;" : "=f"(lo), "=f"(hi) : "l"(v));
}
static __device__ __forceinline__ void fma2(ull& acc, ull w, ull x) {
    asm("fma.rn.f32x2 %0, %1, %2, %0;" : "+l"(acc) : "l"(w), "l"(x));
}

// ---------------------------------------------------------------------------
__global__ void k_first(const float* __restrict__ x,
                        const float* __restrict__ fw,
                        const float* __restrict__ fb) {
    int idx = blockIdx.x * blockDim.x + threadIdx.x;   // over RCH*NPOS
    int r = idx >> 16;
    int p = idx & (NPOS - 1);
    int b = p >> 13;
    int t = p & (TT - 1);
    float v = fw[r] * x[p] + fb[r];
    g_xa[(b * RCH + r) * TT + t] = v;
    g_skip[(b * SCH + r) * TT + t] = 0.f;
}

// ---------------------------------------------------------------------------
__global__ void __launch_bounds__(THR, 1)
k_layer(int l, int d, int flip,
        const float* __restrict__ conv_w, const float* __restrict__ conv_b,
        const float* __restrict__ aux_w,  const float* __restrict__ out_w,
        const float* __restrict__ out_b,  const float* __restrict__ cond,
        const float* __restrict__ mask) {
    extern __shared__ char smraw[];
    ull*   wsh64  = (ull*)smraw;
    char*  xbuf   = smraw + WSH_BYTES;
    ull*   xbuf64 = (ull*)xbuf;
    float* scr    = (float*)xbuf;

    const float* xin  = flip ? g_xb : g_xa;
    float*       xout = flip ? g_xa : g_xb;

    const int tid  = threadIdx.x;
    const int q    = tid >> 7;          // 0..7 : channel quarter-group
    const int pidx = tid & 127;         // position within tile
    const int cb8  = q * 8;             // channel-pair base
    const int p0   = blockIdx.x * POSB; // block base position (128 | 8192)
    const int b    = p0 >> 13;
    const int tb   = p0 & (TT - 1);
    const int p    = p0 + pidx;
    const int t    = tb + pidx;

    const float* cw = conv_w + (size_t)l * GCH * RCH * 3;
    const float* aw = aux_w  + (size_t)l * GCH * ACH;

    // ===== stage conv weights: 2 chunks, two-phase (coalesced + conflict-free)
    for (int h = 0; h < 2; h++) {
        // A1: gmem -> padded scratch, raw order
        for (int idx = tid; idx < 64 * KCONV; idx += THR) {
            int cc = idx / KCONV, m = idx - cc * KCONV;
            int ch = (cc < 32) ? (32 * h + cc) : (32 * h + cc + 32);
            scr[cc * 193 + m] = cw[ch * KCONV + m];
        }
        __syncthreads();
        // A2: scratch -> paired wsh (k-major)
        for (int idx = tid; idx < KCONV * 32; idx += THR) {
            int k  = idx >> 5;
            int cl = idx & 31;
            int ci = k & 63, tap = k >> 6;
            int m  = ci * 3 + tap;
            wsh64[k * 64 + 32 * h + cl] =
                pk2(scr[cl * 193 + m], scr[(32 + cl) * 193 + m]);
        }
        __syncthreads();
    }
    // ===== stage aux weights: 2 chunks
    for (int h = 0; h < 2; h++) {
        for (int idx = tid; idx < 64 * ACH; idx += THR) {
            int cc = idx / ACH, m = idx - cc * ACH;
            int ch = (cc < 32) ? (32 * h + cc) : (32 * h + cc + 32);
            scr[cc * 81 + m] = aw[ch * ACH + m];
        }
        __syncthreads();
        for (int idx = tid; idx < ACH * 32; idx += THR) {
            int j  = idx >> 5;
            int cl = idx & 31;
            wsh64[(KCONV + j) * 64 + 32 * h + cl] =
                pk2(scr[cl * 81 + j], scr[(32 + cl) * 81 + j]);
        }
        __syncthreads();
    }

    // ===== init accumulators with conv bias
    ull acc[8];
    const float* cbp = conv_b + l * GCH;
#pragma unroll
    for (int j = 0; j < 8; j++) acc[j] = pk2(cbp[cb8 + j], cbp[64 + cb8 + j]);

    // ===== dilated conv: per-tap smem staging + accumulate
#pragma unroll 1
    for (int tap = 0; tap < 3; ++tap) {
        const int off = (tap - 1) * d;
        __syncthreads();
        for (int idx = tid; idx < RCH * POSB; idx += THR) {
            int ci = idx >> 7, i = idx & 127;
            int ts = tb + i + off;
            float v = (ts >= 0 && ts < TT) ? xin[(b * RCH + ci) * TT + ts] : 0.f;
            xbuf64[idx] = pk2(v, v);
        }
        __syncthreads();
        const ull* wbase = wsh64 + tap * 64 * 64 + cb8;
#pragma unroll 4
        for (int ci = 0; ci < RCH; ci++) {
            ull xx = xbuf64[ci * POSB + pidx];
            const ull* wr = wbase + ci * 64;
            longlong2 w0 = ((const longlong2*)wr)[0];
            longlong2 w1 = ((const longlong2*)wr)[1];
            longlong2 w2 = ((const longlong2*)wr)[2];
            longlong2 w3 = ((const longlong2*)wr)[3];
            fma2(acc[0], (ull)w0.x, xx); fma2(acc[1], (ull)w0.y, xx);
            fma2(acc[2], (ull)w1.x, xx); fma2(acc[3], (ull)w1.y, xx);
            fma2(acc[4], (ull)w2.x, xx); fma2(acc[5], (ull)w2.y, xx);
            fma2(acc[6], (ull)w3.x, xx); fma2(acc[7], (ull)w3.y, xx);
        }
    }

    // ===== aux (local conditioning)
    __syncthreads();
    for (int idx = tid; idx < ACH * POSB; idx += THR) {
        int j = idx >> 7, i = idx & 127;
        float v = cond[(b * ACH + j) * TT + tb + i];
        xbuf64[idx] = pk2(v, v);
    }
    __syncthreads();
    {
        const ull* wbase = wsh64 + KCONV * 64 + cb8;
#pragma unroll 4
        for (int j = 0; j < ACH; j++) {
            ull xx = xbuf64[j * POSB + pidx];
            const ull* wr = wbase + j * 64;
            longlong2 w0 = ((const longlong2*)wr)[0];
            longlong2 w1 = ((const longlong2*)wr)[1];
            longlong2 w2 = ((const longlong2*)wr)[2];
            longlong2 w3 = ((const longlong2*)wr)[3];
            fma2(acc[0], (ull)w0.x, xx); fma2(acc[1], (ull)w0.y, xx);
            fma2(acc[2], (ull)w1.x, xx); fma2(acc[3], (ull)w1.y, xx);
            fma2(acc[4], (ull)w2.x, xx); fma2(acc[5], (ull)w2.y, xx);
            fma2(acc[6], (ull)w3.x, xx); fma2(acc[7], (ull)w3.y, xx);
        }
    }

    // ===== gated activation
    float z[8];
#pragma unroll
    for (int j = 0; j < 8; j++) {
        float a, g;
        upk2(acc[j], a, g);
        z[j] = tanhf(a) * (1.f / (1.f + expf(-g)));
    }

    __syncthreads();   // all weight/x reads done; repurpose smem

    ull*   zsh64 = (ull*)smraw;                   // 64*128 u64
    ull*   osh64 = (ull*)(smraw + 65536);         // 64*64  u64
    float* scrO  = (float*)(smraw + 98304);       // 128*65 floats

    const float* ow = out_w + (size_t)l * (RCH + SCH) * (GCH / 2);
#pragma unroll
    for (int j = 0; j < 8; j++) zsh64[(cb8 + j) * POSB + pidx] = pk2(z[j], z[j]);
    for (int idx = tid; idx < 128 * 64; idx += THR) {
        int r = idx >> 6, j = idx & 63;
        scrO[r * 65 + j] = ow[r * 64 + j];
    }
    __syncthreads();
    for (int idx = tid; idx < 64 * 64; idx += THR) {
        int j = idx >> 6, r = idx & 63;
        osh64[j * 64 + r] = pk2(scrO[r * 65 + j], scrO[(r + 64) * 65 + j]);
    }
    __syncthreads();

    // ===== out projection: pairs (o[r], o[r+64]) = (residual, skip)
    ull oacc[8];
    const float* obp = out_b + l * (RCH + SCH);
#pragma unroll
    for (int j = 0; j < 8; j++) oacc[j] = pk2(obp[cb8 + j], obp[64 + cb8 + j]);

    {
        const ull* wbase = osh64 + cb8;
#pragma unroll 4
        for (int j = 0; j < GCH / 2; j++) {
            ull zz = zsh64[j * POSB + pidx];
            const ull* wr = wbase + j * 64;
            longlong2 w0 = ((const longlong2*)wr)[0];
            longlong2 w1 = ((const longlong2*)wr)[1];
            longlong2 w2 = ((const longlong2*)wr)[2];
            longlong2 w3 = ((const longlong2*)wr)[3];
            fma2(oacc[0], (ull)w0.x, zz); fma2(oacc[1], (ull)w0.y, zz);
            fma2(oacc[2], (ull)w1.x, zz); fma2(oacc[3], (ull)w1.y, zz);
            fma2(oacc[4], (ull)w2.x, zz); fma2(oacc[5], (ull)w2.y, zz);
            fma2(oacc[6], (ull)w3.x, zz); fma2(oacc[7], (ull)w3.y, zz);
        }
    }

    // ===== mask, residual add, skip accumulate
    const float m = mask[p];
#pragma unroll
    for (int j = 0; j < 8; j++) {
        float res, sk;
        upk2(oacc[j], res, sk);
        int r = cb8 + j;
        size_t xi = (size_t)(b * RCH + r) * TT + t;
        xout[xi] = xin[xi] + res * m;
        size_t si = (size_t)(b * SCH + r) * TT + t;
        g_skip[si] += sk * m;
    }
}

// ---------------------------------------------------------------------------
__global__ void k_last(const float* __restrict__ w1, const float* __restrict__ b1,
                       const float* __restrict__ w2, const float* __restrict__ b2,
                       float* __restrict__ out) {
    __shared__ float w1t[64 * 64];
    __shared__ float w2s[64];
    __shared__ float b1s[64];
    const int tid = threadIdx.x;
    for (int idx = tid; idx < 64 * 64; idx += 256) {
        int i = idx >> 6, j = idx & 63;
        w1t[i * 64 + j] = w1[j * 64 + i];
    }
    if (tid < 64) { w2s[tid] = w2[tid]; b1s[tid] = b1[tid]; }
    __syncthreads();

    const int p = blockIdx.x * 256 + tid;
    const int b = p >> 13;
    const int t = p & (TT - 1);

    float acc[64];
#pragma unroll
    for (int j = 0; j < 64; j++) acc[j] = b1s[j];

    const float* sp = g_skip + (size_t)b * SCH * TT + t;
    for (int i = 0; i < 64; i++) {
        float sv = fmaxf(sp[i * TT], 0.f);
#pragma unroll
        for (int j = 0; j < 64; j += 4) {
            float4 w = *(const float4*)(w1t + i * 64 + j);
            acc[j]     = fmaf(w.x, sv, acc[j]);
            acc[j + 1] = fmaf(w.y, sv, acc[j + 1]);
            acc[j + 2] = fmaf(w.z, sv, acc[j + 2]);
            acc[j + 3] = fmaf(w.w, sv, acc[j + 3]);
        }
    }
    float y = b2[0];
#pragma unroll
    for (int j = 0; j < 64; j++) y = fmaf(w2s[j], fmaxf(acc[j], 0.f), y);
    out[p] = y;
}

// ---------------------------------------------------------------------------
extern "C" void kernel_launch(void* const* d_in, const int* in_sizes, int n_in,
                              void* d_out, int out_size) {
    const float* x      = (const float*)d_in[0];
    const float* x_mask = (const float*)d_in[1];
    const float* c      = (const float*)d_in[2];
    const float* fw     = (const float*)d_in[3];
    const float* fb     = (const float*)d_in[4];
    const float* conv_w = (const float*)d_in[5];
    const float* conv_b = (const float*)d_in[6];
    const float* aux_w  = (const float*)d_in[7];
    const float* out_w  = (const float*)d_in[8];
    const float* out_b  = (const float*)d_in[9];
    const float* w1     = (const float*)d_in[10];
    const float* b1     = (const float*)d_in[11];
    const float* w2     = (const float*)d_in[12];
    const float* b2     = (const float*)d_in[13];

    cudaFuncSetAttribute(k_layer, cudaFuncAttributeMaxDynamicSharedMemorySize,
                         SMEM_LAYER);

    k_first<<<(RCH * NPOS) / 512, 512>>>(x, fw, fb);

    for (int l = 0; l < NLAYERS; l++) {
        int d = 1 << (l % 10);
        k_layer<<<NPOS / POSB, THR, SMEM_LAYER>>>(
            l, d, l & 1, conv_w, conv_b, aux_w, out_w, out_b, c, x_mask);
    }

    k_last<<<NPOS / 256, 256>>>(w1, b1, w2, b2, (float*)d_out);
}

// round 3
// speedup vs baseline: 1.4166x; 1.4166x over previous
#include <cuda_runtime.h>

#define RCH 64
#define GCH 128
#define ACH 80
#define SCH 64
#define TT 8192
#define BB 8
#define NPOS (BB*TT)      // 65536
#define NLAYERS 30
#define POSB 256          // positions per block
#define PPB 128           // position-pairs per block
#define THR 512
#define KCONV 192

// smem: wsh float[272*128] (139264 B) + xbuf (80*128 u64 = 81920 B)
#define WSH_BYTES (272*128*4)
#define XBUF_BYTES (ACH*PPB*8)
#define SMEM_LAYER (WSH_BYTES + XBUF_BYTES)   // 221184

__device__ float g_xa[BB*RCH*TT];
__device__ float g_xb[BB*RCH*TT];
__device__ float g_skip[BB*SCH*TT];

typedef unsigned long long ull;

static __device__ __forceinline__ ull pk2(float lo, float hi) {
    ull r; asm("mov.b64 %0, {%1, %2};" : "=l"(r) : "f"(lo), "f"(hi)); return r;
}
static __device__ __forceinline__ void upk2(ull v, float& lo, float& hi) {
    asm("mov.b64 {%0, %1}, %2;" : "=f"(lo), "=f"(hi) : "l"(v));
}
static __device__ __forceinline__ void fma2(ull& acc, ull w, ull x) {
    asm("fma.rn.f32x2 %0, %1, %2, %0;" : "+l"(acc) : "l"(w), "l"(x));
}
static __device__ __forceinline__ ull mul2(ull a, ull b) {
    ull r; asm("mul.rn.f32x2 %0, %1, %2;" : "=l"(r) : "l"(a), "l"(b)); return r;
}
static __device__ __forceinline__ ull add2(ull a, ull b) {
    ull r; asm("add.rn.f32x2 %0, %1, %2;" : "=l"(r) : "l"(a), "l"(b)); return r;
}
static __device__ __forceinline__ float tanhapx(float x) {
    float r; asm("tanh.approx.f32 %0, %1;" : "=f"(r) : "f"(x)); return r;
}
// gate = tanh(a) * sigmoid(b),  sigmoid(b) = 0.5*tanh(0.5*b)+0.5
static __device__ __forceinline__ float gatef(float a, float b) {
    return tanhapx(a) * (0.5f * tanhapx(0.5f * b) + 0.5f);
}

// ---------------------------------------------------------------------------
__global__ void k_first(const float* __restrict__ x,
                        const float* __restrict__ fw,
                        const float* __restrict__ fb) {
    int idx = blockIdx.x * blockDim.x + threadIdx.x;
    int r = idx >> 16;
    int p = idx & (NPOS - 1);
    int b = p >> 13;
    int t = p & (TT - 1);
    float v = fw[r] * x[p] + fb[r];
    g_xa[(b * RCH + r) * TT + t] = v;
    g_skip[(b * SCH + r) * TT + t] = 0.f;
}

// ---------------------------------------------------------------------------
// fused layer. Thread (g = tid&15, s = tid>>4) owns channels {4g..4g+3,
// 64+4g..64+4g+3} and position-pairs 4s..4s+3 (positions 8s..8s+7).
// f32x2 lanes = two consecutive positions.
// ---------------------------------------------------------------------------
__global__ void __launch_bounds__(THR, 1)
k_layer(int l, int d, int flip,
        const float* __restrict__ conv_w, const float* __restrict__ conv_b,
        const float* __restrict__ aux_w,  const float* __restrict__ out_w,
        const float* __restrict__ out_b,  const float* __restrict__ cond,
        const float* __restrict__ mask) {
    extern __shared__ char smraw[];
    float* wsh    = (float*)smraw;                    // [272][128]
    ull*   xbuf64 = (ull*)(smraw + WSH_BYTES);        // [80][128] pairs
    float* scr    = (float*)(smraw + WSH_BYTES);      // staging scratch

    const float* xin  = flip ? g_xb : g_xa;
    float*       xout = flip ? g_xa : g_xb;

    const int tid = threadIdx.x;
    const int g   = tid & 15;
    const int s   = tid >> 4;           // 0..31
    const int c4  = 4 * g;
    const int p0  = blockIdx.x * POSB;
    const int b   = p0 >> 13;
    const int tb  = p0 & (TT - 1);

    const float* cw = conv_w + (size_t)l * GCH * RCH * 3;
    const float* aw = aux_w  + (size_t)l * GCH * ACH;

    // ===== stage conv weights (2 halves, two-phase conflict-free) ==========
    for (int h = 0; h < 2; h++) {
        for (int idx = tid; idx < 64 * KCONV; idx += THR) {
            int cc = idx / KCONV, m = idx - cc * KCONV;
            scr[cc * 193 + m] = cw[(64 * h + cc) * KCONV + m];
        }
        __syncthreads();
        for (int idx = tid; idx < KCONV * 64; idx += THR) {
            int k = idx >> 6, cc = idx & 63;
            int ci = k & 63, tap = k >> 6;
            wsh[k * 128 + 64 * h + cc] = scr[cc * 193 + ci * 3 + tap];
        }
        __syncthreads();
    }
    // ===== stage aux weights ================================================
    for (int h = 0; h < 2; h++) {
        for (int idx = tid; idx < 64 * ACH; idx += THR) {
            int cc = idx / ACH, j = idx - cc * ACH;
            scr[cc * 81 + j] = aw[(64 * h + cc) * ACH + j];
        }
        __syncthreads();
        for (int idx = tid; idx < ACH * 64; idx += THR) {
            int j = idx >> 6, cc = idx & 63;
            wsh[(KCONV + j) * 128 + 64 * h + cc] = scr[cc * 81 + j];
        }
        __syncthreads();
    }

    // ===== init accumulators with conv bias =================================
    ull acc[8][4];
    const float* cbp = conv_b + l * GCH;
#pragma unroll
    for (int i = 0; i < 4; i++) {
        float blo = cbp[c4 + i], bhi = cbp[64 + c4 + i];
        ull plo = pk2(blo, blo), phi = pk2(bhi, bhi);
#pragma unroll
        for (int u = 0; u < 4; u++) { acc[i][u] = plo; acc[4 + i][u] = phi; }
    }

    // ===== dilated conv: per-tap stage + accumulate ==========================
#pragma unroll 1
    for (int tap = 0; tap < 3; ++tap) {
        const int off = (tap - 1) * d;
        __syncthreads();
        for (int idx = tid; idx < RCH * PPB; idx += THR) {
            int ci = idx >> 7, pp = idx & 127;
            const float* xrow = xin + (size_t)(b * RCH + ci) * TT;
            int t0 = tb + 2 * pp + off;
            float v0 = ((unsigned)t0 < TT) ? xrow[t0] : 0.f;
            float v1 = ((unsigned)(t0 + 1) < TT) ? xrow[t0 + 1] : 0.f;
            xbuf64[idx] = pk2(v0, v1);
        }
        __syncthreads();
        const float* wb = wsh + tap * 64 * 128 + c4;
        const ull*   xb = xbuf64 + 4 * s;
#pragma unroll 2
        for (int ci = 0; ci < RCH; ci++) {
            float4 wl = *(const float4*)(wb + ci * 128);
            float4 wh = *(const float4*)(wb + ci * 128 + 64);
            ull wd[8];
            wd[0] = pk2(wl.x, wl.x); wd[1] = pk2(wl.y, wl.y);
            wd[2] = pk2(wl.z, wl.z); wd[3] = pk2(wl.w, wl.w);
            wd[4] = pk2(wh.x, wh.x); wd[5] = pk2(wh.y, wh.y);
            wd[6] = pk2(wh.z, wh.z); wd[7] = pk2(wh.w, wh.w);
            ulonglong2 x01 = *(const ulonglong2*)(xb + ci * PPB);
            ulonglong2 x23 = *(const ulonglong2*)(xb + ci * PPB + 2);
            ull xx[4] = {x01.x, x01.y, x23.x, x23.y};
#pragma unroll
            for (int i = 0; i < 8; i++)
#pragma unroll
                for (int u = 0; u < 4; u++) fma2(acc[i][u], wd[i], xx[u]);
        }
    }

    // ===== aux (local conditioning) =========================================
    __syncthreads();
    for (int idx = tid; idx < ACH * PPB; idx += THR) {
        int j = idx >> 7, pp = idx & 127;
        float2 v = *(const float2*)(cond + (size_t)(b * ACH + j) * TT + tb + 2 * pp);
        xbuf64[idx] = pk2(v.x, v.y);
    }
    __syncthreads();
    {
        const float* wb = wsh + KCONV * 128 + c4;
        const ull*   xb = xbuf64 + 4 * s;
#pragma unroll 2
        for (int j = 0; j < ACH; j++) {
            float4 wl = *(const float4*)(wb + j * 128);
            float4 wh = *(const float4*)(wb + j * 128 + 64);
            ull wd[8];
            wd[0] = pk2(wl.x, wl.x); wd[1] = pk2(wl.y, wl.y);
            wd[2] = pk2(wl.z, wl.z); wd[3] = pk2(wl.w, wl.w);
            wd[4] = pk2(wh.x, wh.x); wd[5] = pk2(wh.y, wh.y);
            wd[6] = pk2(wh.z, wh.z); wd[7] = pk2(wh.w, wh.w);
            ulonglong2 x01 = *(const ulonglong2*)(xb + j * PPB);
            ulonglong2 x23 = *(const ulonglong2*)(xb + j * PPB + 2);
            ull xx[4] = {x01.x, x01.y, x23.x, x23.y};
#pragma unroll
            for (int i = 0; i < 8; i++)
#pragma unroll
                for (int u = 0; u < 4; u++) fma2(acc[i][u], wd[i], xx[u]);
        }
    }

    __syncthreads();   // all wsh/xbuf reads done; repurpose smem

    ull*   zsh64 = (ull*)smraw;                   // [64][128] pairs (64 KB)
    float* osh   = (float*)(smraw + 65536);       // [64][128]       (32 KB)
    float* scrO  = (float*)(smraw + 98304);       // 128*65 floats   (33 KB)

    // ===== gate -> zsh, stage out weights ===================================
#pragma unroll
    for (int i = 0; i < 4; i++)
#pragma unroll
        for (int u = 0; u < 4; u++) {
            float a0, a1, b0, b1;
            upk2(acc[i][u], a0, a1);
            upk2(acc[4 + i][u], b0, b1);
            zsh64[(c4 + i) * PPB + 4 * s + u] = pk2(gatef(a0, b0), gatef(a1, b1));
        }
    const float* ow = out_w + (size_t)l * (RCH + SCH) * (GCH / 2);
    for (int idx = tid; idx < 128 * 64; idx += THR) {
        int r = idx >> 6, j = idx & 63;
        scrO[r * 65 + j] = ow[idx];
    }
    __syncthreads();
    for (int idx = tid; idx < 64 * 128; idx += THR) {
        int j = idx >> 7, r = idx & 127;
        osh[j * 128 + r] = scrO[r * 65 + j];
    }
    __syncthreads();

    // ===== out projection ====================================================
    ull oacc[8][4];
    const float* obp = out_b + l * (RCH + SCH);
#pragma unroll
    for (int i = 0; i < 4; i++) {
        float blo = obp[c4 + i], bhi = obp[64 + c4 + i];
        ull plo = pk2(blo, blo), phi = pk2(bhi, bhi);
#pragma unroll
        for (int u = 0; u < 4; u++) { oacc[i][u] = plo; oacc[4 + i][u] = phi; }
    }
    {
        const float* wb = osh + c4;
        const ull*   zb = zsh64 + 4 * s;
#pragma unroll 2
        for (int j = 0; j < GCH / 2; j++) {
            float4 wl = *(const float4*)(wb + j * 128);
            float4 wh = *(const float4*)(wb + j * 128 + 64);
            ull wd[8];
            wd[0] = pk2(wl.x, wl.x); wd[1] = pk2(wl.y, wl.y);
            wd[2] = pk2(wl.z, wl.z); wd[3] = pk2(wl.w, wl.w);
            wd[4] = pk2(wh.x, wh.x); wd[5] = pk2(wh.y, wh.y);
            wd[6] = pk2(wh.z, wh.z); wd[7] = pk2(wh.w, wh.w);
            ulonglong2 z01 = *(const ulonglong2*)(zb + j * PPB);
            ulonglong2 z23 = *(const ulonglong2*)(zb + j * PPB + 2);
            ull zz[4] = {z01.x, z01.y, z23.x, z23.y};
#pragma unroll
            for (int i = 0; i < 8; i++)
#pragma unroll
                for (int u = 0; u < 4; u++) fma2(oacc[i][u], wd[i], zz[u]);
        }
    }

    // ===== mask, residual add, skip accumulate (packed 64-bit) ==============
#pragma unroll
    for (int u = 0; u < 4; u++) {
        const int t2 = tb + 8 * s + 2 * u;
        const ull mpair = *(const ull*)(mask + p0 + 8 * s + 2 * u);
#pragma unroll
        for (int i = 0; i < 4; i++) {
            int r = c4 + i;
            size_t xi = (size_t)(b * RCH + r) * TT + t2;
            ull res = mul2(oacc[i][u], mpair);
            *(ull*)(xout + xi) = add2(*(const ull*)(xin + xi), res);
            size_t si = (size_t)(b * SCH + r) * TT + t2;
            ull sk = mul2(oacc[4 + i][u], mpair);
            *(ull*)(g_skip + si) = add2(*(const ull*)(g_skip + si), sk);
        }
    }
}

// ---------------------------------------------------------------------------
__global__ void k_last(const float* __restrict__ w1, const float* __restrict__ b1,
                       const float* __restrict__ w2, const float* __restrict__ b2,
                       float* __restrict__ out) {
    __shared__ float w1t[64 * 64];
    __shared__ float w2s[64];
    __shared__ float b1s[64];
    const int tid = threadIdx.x;
    for (int idx = tid; idx < 64 * 64; idx += 256) {
        int i = idx >> 6, j = idx & 63;
        w1t[i * 64 + j] = w1[j * 64 + i];
    }
    if (tid < 64) { w2s[tid] = w2[tid]; b1s[tid] = b1[tid]; }
    __syncthreads();

    const int p = blockIdx.x * 256 + tid;
    const int b = p >> 13;
    const int t = p & (TT - 1);

    float acc[64];
#pragma unroll
    for (int j = 0; j < 64; j++) acc[j] = b1s[j];

    const float* sp = g_skip + (size_t)b * SCH * TT + t;
    for (int i = 0; i < 64; i++) {
        float sv = fmaxf(sp[i * TT], 0.f);
#pragma unroll
        for (int j = 0; j < 64; j += 4) {
            float4 w = *(const float4*)(w1t + i * 64 + j);
            acc[j]     = fmaf(w.x, sv, acc[j]);
            acc[j + 1] = fmaf(w.y, sv, acc[j + 1]);
            acc[j + 2] = fmaf(w.z, sv, acc[j + 2]);
            acc[j + 3] = fmaf(w.w, sv, acc[j + 3]);
        }
    }
    float y = b2[0];
#pragma unroll
    for (int j = 0; j < 64; j++) y = fmaf(w2s[j], fmaxf(acc[j], 0.f), y);
    out[p] = y;
}

// ---------------------------------------------------------------------------
extern "C" void kernel_launch(void* const* d_in, const int* in_sizes, int n_in,
                              void* d_out, int out_size) {
    const float* x      = (const float*)d_in[0];
    const float* x_mask = (const float*)d_in[1];
    const float* c      = (const float*)d_in[2];
    const float* fw     = (const float*)d_in[3];
    const float* fb     = (const float*)d_in[4];
    const float* conv_w = (const float*)d_in[5];
    const float* conv_b = (const float*)d_in[6];
    const float* aux_w  = (const float*)d_in[7];
    const float* out_w  = (const float*)d_in[8];
    const float* out_b  = (const float*)d_in[9];
    const float* w1     = (const float*)d_in[10];
    const float* b1     = (const float*)d_in[11];
    const float* w2     = (const float*)d_in[12];
    const float* b2     = (const float*)d_in[13];

    cudaFuncSetAttribute(k_layer, cudaFuncAttributeMaxDynamicSharedMemorySize,
                         SMEM_LAYER);

    k_first<<<(RCH * NPOS) / 512, 512>>>(x, fw, fb);

    for (int l = 0; l < NLAYERS; l++) {
        int d = 1 << (l % 10);
        k_layer<<<NPOS / POSB, THR, SMEM_LAYER>>>(
            l, d, l & 1, conv_w, conv_b, aux_w, out_w, out_b, c, x_mask);
    }

    k_last<<<NPOS / 256, 256>>>(w1, b1, w2, b2, (float*)d_out);
}